// round 3
// baseline (speedup 1.0000x reference)
#include <cuda_runtime.h>

// Problem constants (fixed by the dataset)
static constexpr int B  = 4;
static constexpr int C  = 128;     // channels in == channels out (K)
static constexpr int N  = 65536;
static constexpr int NN = 3;       // neighbors
static constexpr int NM = 16;      // NUM_MATRIX
static constexpr float BN_EPS = 1e-5f;

static constexpr int TILE_N2 = 64;                    // n-points per k_gather block
static constexpr int NBLK2   = (N / TILE_N2) * B;     // 4096 gather blocks

// ---- device scratch (allocation-free per harness rules) ----
__device__ float g_Wm[C * C];                         // mean weight matrix [c][k]
__device__ float g_Y[(size_t)B * N * C];              // GEMM result, [b][n][k] row-major
__device__ float g_feat[(size_t)B * N * C];           // neighbor-averaged features [b][n][k]
__device__ float g_psum[(size_t)NBLK2 * C];           // per-block partial sums
__device__ float g_psq[(size_t)NBLK2 * C];            // per-block partial sum-of-squares
__device__ float g_scale[C];
__device__ float g_bias[C];

// ---------------------------------------------------------------------------
// K0: Wm[c][k] = mean_m W[c][k][m]
// ---------------------------------------------------------------------------
__global__ void k_prep(const float* __restrict__ W) {
    int id = blockIdx.x * blockDim.x + threadIdx.x;   // 0 .. C*C-1
    if (id < C * C) {
        const float* w = W + (size_t)id * NM;         // 16 contiguous floats
        float s = 0.f;
        #pragma unroll
        for (int m = 0; m < NM; m++) s += w[m];
        g_Wm[id] = s * (1.0f / NM);
    }
}

// ---------------------------------------------------------------------------
// K1: Y[b][n][k] = sum_c fea[b][c][n] * Wm[c][k]
// Tiled GEMM: BM=64 (n), BN=128 (k), BK=16 (c); 256 threads, 8x4 micro-tile.
// ---------------------------------------------------------------------------
__global__ __launch_bounds__(256) void k_gemm(const float* __restrict__ fea) {
    __shared__ float As[16][64];     // [c][n] slice of fea
    __shared__ float Bs[16][128];    // [c][k] slice of Wm

    const int b  = blockIdx.y;
    const int n0 = blockIdx.x * 64;
    const int t  = threadIdx.x;
    const int tx = t & 31;           // k-direction (4 k per thread)
    const int ty = t >> 5;           // n-direction (8 n per thread)

    const float* feaB = fea + (size_t)b * C * N;

    float acc[8][4];
    #pragma unroll
    for (int i = 0; i < 8; i++)
        #pragma unroll
        for (int j = 0; j < 4; j++) acc[i][j] = 0.f;

    for (int c0 = 0; c0 < C; c0 += 16) {
        // load A tile: 16x64, coalesced along n
        #pragma unroll
        for (int r = 0; r < 4; r++) {
            int lin = t + r * 256;
            int cc = lin >> 6, nn = lin & 63;
            As[cc][nn] = feaB[(size_t)(c0 + cc) * N + n0 + nn];
        }
        // load B tile: 16x128, coalesced along k
        #pragma unroll
        for (int r = 0; r < 8; r++) {
            int lin = t + r * 256;
            int cc = lin >> 7, kk = lin & 127;
            Bs[cc][kk] = g_Wm[(c0 + cc) * C + kk];
        }
        __syncthreads();

        #pragma unroll
        for (int cc = 0; cc < 16; cc++) {
            float a[8];
            #pragma unroll
            for (int i = 0; i < 8; i++) a[i] = As[cc][ty * 8 + i];   // warp-broadcast
            float4 bv = *reinterpret_cast<const float4*>(&Bs[cc][tx * 4]);
            #pragma unroll
            for (int i = 0; i < 8; i++) {
                acc[i][0] += a[i] * bv.x;
                acc[i][1] += a[i] * bv.y;
                acc[i][2] += a[i] * bv.z;
                acc[i][3] += a[i] * bv.w;
            }
        }
        __syncthreads();
    }

    float* Yb = g_Y + ((size_t)b * N + n0) * C;
    #pragma unroll
    for (int i = 0; i < 8; i++) {
        float4 v = make_float4(acc[i][0], acc[i][1], acc[i][2], acc[i][3]);
        *reinterpret_cast<float4*>(&Yb[(size_t)(ty * 8 + i) * C + tx * 4]) = v;
    }
}

// ---------------------------------------------------------------------------
// K2: feat[b][n][:] = (Y[b][n][:] + sum_m Y[b][ring[b][n][m]][:]) / 4
//     + per-block partial sums / sums-of-squares per channel (deterministic).
// One warp handles 8 n-points; each lane owns 4 channels (float4).
// ring_n is int32 on the wire (JAX x64 disabled downcasts int64 -> int32).
// Indices are masked with N-1 (power of two): no-op for valid indices, and
// converts a wrong-dtype hypothesis into a visible rel_err failure instead
// of an illegal memory access.
// ---------------------------------------------------------------------------
__global__ __launch_bounds__(256) void k_gather(const int* __restrict__ ring) {
    __shared__ float ssum[8][128];
    __shared__ float ssq[8][128];

    const int b    = blockIdx.y;
    const int n0   = blockIdx.x * TILE_N2;
    const int t    = threadIdx.x;
    const int lane = t & 31;
    const int w    = t >> 5;

    const float4* Yb = reinterpret_cast<const float4*>(g_Y + (size_t)b * N * C);
    float4*       Fb = reinterpret_cast<float4*>(g_feat + (size_t)b * N * C);
    const int* rb = ring + (size_t)b * N * NN;

    float4 s = make_float4(0.f, 0.f, 0.f, 0.f);
    float4 q = make_float4(0.f, 0.f, 0.f, 0.f);

    #pragma unroll
    for (int i = 0; i < 8; i++) {
        const int n = n0 + w * 8 + i;
        const int* rp = rb + (size_t)n * NN;
        const int j0 = rp[0] & (N - 1);
        const int j1 = rp[1] & (N - 1);
        const int j2 = rp[2] & (N - 1);

        float4 v  = Yb[(size_t)n  * 32 + lane];
        float4 a0 = Yb[(size_t)j0 * 32 + lane];
        float4 a1 = Yb[(size_t)j1 * 32 + lane];
        float4 a2 = Yb[(size_t)j2 * 32 + lane];

        float4 f;
        f.x = (v.x + a0.x + a1.x + a2.x) * 0.25f;
        f.y = (v.y + a0.y + a1.y + a2.y) * 0.25f;
        f.z = (v.z + a0.z + a1.z + a2.z) * 0.25f;
        f.w = (v.w + a0.w + a1.w + a2.w) * 0.25f;

        Fb[(size_t)n * 32 + lane] = f;

        s.x += f.x; s.y += f.y; s.z += f.z; s.w += f.w;
        q.x += f.x * f.x; q.y += f.y * f.y; q.z += f.z * f.z; q.w += f.w * f.w;
    }

    // stage per-warp partials (vectorized, conflict-free)
    *reinterpret_cast<float4*>(&ssum[w][lane * 4]) = s;
    *reinterpret_cast<float4*>(&ssq[w][lane * 4])  = q;
    __syncthreads();

    const int bid = blockIdx.y * gridDim.x + blockIdx.x;
    if (t < 128) {
        float acc = 0.f;
        #pragma unroll
        for (int ww = 0; ww < 8; ww++) acc += ssum[ww][t];
        g_psum[(size_t)bid * C + t] = acc;
    } else {
        const int k = t - 128;
        float acc = 0.f;
        #pragma unroll
        for (int ww = 0; ww < 8; ww++) acc += ssq[ww][k];
        g_psq[(size_t)bid * C + k] = acc;
    }
}

// ---------------------------------------------------------------------------
// K3: fold partials -> per-channel scale/bias. One block per channel.
// ---------------------------------------------------------------------------
__global__ void k_stats(const float* __restrict__ gamma, const float* __restrict__ beta) {
    const int k = blockIdx.x;
    const int t = threadIdx.x;

    float s = 0.f, q = 0.f;
    for (int i = t; i < NBLK2; i += 256) {
        s += g_psum[(size_t)i * C + k];
        q += g_psq[(size_t)i * C + k];
    }
    __shared__ float rs[256], rq[256];
    rs[t] = s; rq[t] = q;
    __syncthreads();
    for (int off = 128; off > 0; off >>= 1) {
        if (t < off) { rs[t] += rs[t + off]; rq[t] += rq[t + off]; }
        __syncthreads();
    }
    if (t == 0) {
        const float inv = 1.0f / ((float)B * (float)N);
        float mu  = rs[0] * inv;
        float var = rq[0] * inv - mu * mu;
        float sc  = gamma[k] * rsqrtf(var + BN_EPS);
        g_scale[k] = sc;
        g_bias[k]  = beta[k] - mu * sc;
    }
}

// ---------------------------------------------------------------------------
// K4: out[b][k][n] = relu(feat[b][n][k] * scale[k] + bias[k])
// Classic 32x32 padded-smem transpose, block (32,8).
// ---------------------------------------------------------------------------
__global__ __launch_bounds__(256) void k_out(float* __restrict__ out) {
    __shared__ float tile[32][33];

    const int b  = blockIdx.z;
    const int n0 = blockIdx.x * 32;
    const int k0 = blockIdx.y * 32;
    const int tx = threadIdx.x;
    const int ty = threadIdx.y;

    const float* Fb = g_feat + (size_t)b * N * C;
    #pragma unroll
    for (int j = 0; j < 4; j++) {
        int n = n0 + ty + 8 * j;
        tile[ty + 8 * j][tx] = Fb[(size_t)n * C + k0 + tx];
    }
    __syncthreads();

    float* ob = out + (size_t)b * C * N;
    #pragma unroll
    for (int j = 0; j < 4; j++) {
        int k = k0 + ty + 8 * j;
        float v = tile[tx][ty + 8 * j];
        v = fmaxf(v * g_scale[k] + g_bias[k], 0.f);
        ob[(size_t)k * N + n0 + tx] = v;
    }
}

// ---------------------------------------------------------------------------
extern "C" void kernel_launch(void* const* d_in, const int* in_sizes, int n_in,
                              void* d_out, int out_size) {
    const float* fea   = (const float*)d_in[0];
    const int*   ring  = (const int*)d_in[1];      // int32 (JAX x64-disabled)
    const float* W     = (const float*)d_in[2];
    const float* gamma = (const float*)d_in[3];
    const float* beta  = (const float*)d_in[4];
    float*       out   = (float*)d_out;

    (void)in_sizes; (void)n_in; (void)out_size;

    k_prep<<<64, 256>>>(W);

    dim3 g1(N / 64, B);
    k_gemm<<<g1, 256>>>(fea);

    dim3 g2(N / TILE_N2, B);
    k_gather<<<g2, 256>>>(ring);

    k_stats<<<C, 256>>>(gamma, beta);

    dim3 g4(N / 32, C / 32, B);
    k_out<<<g4, dim3(32, 8)>>>(out);
}